// round 1
// baseline (speedup 1.0000x reference)
#include <cuda_runtime.h>
#include <cstdint>

#define FULL_MASK 0xFFFFFFFFu

// One warp per batch row. Backward affine scan over T timesteps, 32 at a time
// via warp suffix-scan of affine map composition:
//   x_t = A_t * x_{t+1} + B_t
// Both recurrences (lambda-return, sum-rewards) share the same A.
__global__ void td_scan_kernel(const float* __restrict__ values,   // [B, T+1]
                               const float* __restrict__ rewards,  // [B, T]
                               const float* __restrict__ dones,    // [B, T]
                               const float* __restrict__ raw_gamma,// [1]
                               const float* __restrict__ raw_lambd,// [>=T]
                               const int*   __restrict__ p_start,  // [1]
                               float* __restrict__ out_lam,        // [B, T+1]
                               float* __restrict__ out_sum,        // [B, T]
                               int B, int T)
{
    extern __shared__ float s_l[];  // T floats: lambda(t)

    const int tid   = threadIdx.x;
    const int lane  = tid & 31;
    const int wid   = tid >> 5;
    const int warps = blockDim.x >> 5;
    const int row   = blockIdx.x * warps + wid;

    const int s0 = p_start ? p_start[0] : 0;

    // Precompute lambda(t) table into shared memory (broadcast across warps).
    // 2*sigmoid(x)-1 == tanh(x/2)
    for (int t = tid; t < T; t += blockDim.x) {
        float x = raw_lambd[s0 + t];
        s_l[t] = 0.95f + 0.05f * tanhf(0.5f * x);
    }
    __syncthreads();

    if (row >= B) return;

    const float g = 0.99f + 0.01f * tanhf(0.5f * raw_gamma[0]);

    const float* vrow = values  + (size_t)row * (size_t)(T + 1);
    const float* rrow = rewards + (size_t)row * (size_t)T;
    const float* drow = dones   + (size_t)row * (size_t)T;
    float* lrow = out_lam + (size_t)row * (size_t)(T + 1);
    float* srow = out_sum + (size_t)row * (size_t)T;

    const float vlast = vrow[T];
    if (lane == 0) lrow[T] = vlast;   // lambda_returns[:, T] = values[:, T]

    float c_lam = vlast;   // carry for lambda recurrence (x_{t+1})
    float c_sum = 0.0f;    // carry for sum recurrence

    // First (possibly partial) segment start
    const int seg0 = ((T + 31) / 32 - 1) * 32;

    for (int seg = seg0; seg >= 0; seg -= 32) {
        const int t = seg + lane;
        const bool ok = (t < T);

        float r  = 0.0f, d = 0.0f, vn = 0.0f, l = 0.0f;
        if (ok) {
            r  = rrow[t];
            d  = drow[t];
            vn = vrow[t + 1];
            l  = s_l[t];
        }

        // Per-step affine map: x_t = A * x_{t+1} + B
        float cont = g - g * d;            // gamma * (1 - done)
        float A  = ok ? (cont * l) : 1.0f; // identity map for padding lanes
        float Bl = ok ? fmaf(cont - A, vn, r) : 0.0f;  // cont*(1-l)*vn + r
        float Bs = ok ? r : 0.0f;

        // Inclusive suffix scan of affine composition:
        // lane i ends with map m_i ∘ m_{i+1} ∘ ... ∘ m_31
        #pragma unroll
        for (int len = 1; len < 32; len <<= 1) {
            float Ao  = __shfl_down_sync(FULL_MASK, A,  len);
            float Blo = __shfl_down_sync(FULL_MASK, Bl, len);
            float Bso = __shfl_down_sync(FULL_MASK, Bs, len);
            if (lane + len < 32) {
                Bl = fmaf(A, Blo, Bl);
                Bs = fmaf(A, Bso, Bs);
                A  = A * Ao;
            }
        }

        // Apply composed map to the carry from the segment to the right.
        float lamv = fmaf(A, c_lam, Bl);
        float sumv = fmaf(A, c_sum, Bs);
        if (ok) {
            lrow[t] = lamv;
            srow[t] = sumv;
        }

        // New carry = value at the leftmost timestep of this segment (lane 0).
        c_lam = __shfl_sync(FULL_MASK, lamv, 0);
        c_sum = __shfl_sync(FULL_MASK, sumv, 0);
    }
}

extern "C" void kernel_launch(void* const* d_in, const int* in_sizes, int n_in,
                              void* d_out, int out_size)
{
    const float* values    = (const float*)d_in[0];
    const float* rewards   = (const float*)d_in[1];
    const float* dones     = (const float*)d_in[2];
    const float* raw_gamma = (const float*)d_in[3];
    const float* raw_lambd = (const float*)d_in[4];
    const int*   p_start   = (n_in > 5) ? (const int*)d_in[5] : nullptr;

    const int T = in_sizes[4];          // raw_lambd has T elements
    const int B = in_sizes[1] / T;      // rewards is B*T

    float* out_lam = (float*)d_out;                       // B*(T+1)
    float* out_sum = (float*)d_out + (size_t)B * (T + 1); // B*T

    const int warps_per_block = 8;
    const int threads = warps_per_block * 32;
    const int blocks  = (B + warps_per_block - 1) / warps_per_block;
    const size_t smem = (size_t)T * sizeof(float);

    td_scan_kernel<<<blocks, threads, smem>>>(
        values, rewards, dones, raw_gamma, raw_lambd, p_start,
        out_lam, out_sum, B, T);
}

// round 2
// speedup vs baseline: 1.4773x; 1.4773x over previous
#include <cuda_runtime.h>
#include <cstdint>

#define FULL_MASK 0xFFFFFFFFu
#define KPL 8   // timesteps per lane; warp segment = 32*KPL = 256

// Precomputed per-timestep lambda and gamma (written by prep_kernel).
__device__ float g_lam_tab[16384];
__device__ float g_gamma_c;

__global__ void prep_kernel(const float* __restrict__ raw_gamma,
                            const float* __restrict__ raw_lambd,
                            const int*   __restrict__ p_start,
                            int T)
{
    int t = blockIdx.x * blockDim.x + threadIdx.x;
    if (t == 0) {
        // 2*sigmoid(x)-1 == tanh(x/2)
        g_gamma_c = 0.99f + 0.01f * tanhf(0.5f * raw_gamma[0]);
    }
    int s0 = p_start ? p_start[0] : 0;
    if (t < T) {
        g_lam_tab[t] = 0.95f + 0.05f * tanhf(0.5f * raw_lambd[s0 + t]);
    }
}

// One warp per batch row. Backward affine scan:
//   x_t = A_t * x_{t+1} + B_t,  A_t = g*(1-d_t)*l_t shared by both recurrences.
// Each lane owns KPL consecutive timesteps; local map composition + one
// 5-round warp suffix scan handles 32*KPL timesteps per iteration.
__global__ __launch_bounds__(128)
void td_scan_kernel(const float* __restrict__ values,   // [B, T+1]
                    const float* __restrict__ rewards,  // [B, T]
                    const float* __restrict__ dones,    // [B, T]
                    float* __restrict__ out_lam,        // [B, T+1]
                    float* __restrict__ out_sum,        // [B, T]
                    int B, int T)
{
    const int lane  = threadIdx.x & 31;
    const int wid   = threadIdx.x >> 5;
    const int warps = blockDim.x >> 5;
    const int row   = blockIdx.x * warps + wid;
    if (row >= B) return;

    const float g = g_gamma_c;

    const float* vrow = values  + (size_t)row * (size_t)(T + 1);
    const float* rrow = rewards + (size_t)row * (size_t)T;
    const float* drow = dones   + (size_t)row * (size_t)T;
    float* lrow = out_lam + (size_t)row * (size_t)(T + 1);
    float* srow = out_sum + (size_t)row * (size_t)T;

    const float vlast = vrow[T];
    if (lane == 0) lrow[T] = vlast;

    float c_lam = vlast;
    float c_sum = 0.0f;

    const int SEG = 32 * KPL;
    const int nseg = (T + SEG - 1) / SEG;

    for (int s = nseg - 1; s >= 0; --s) {
        const int base = s * SEG + lane * KPL;   // first timestep of this lane
        const bool full = (base + KPL <= T);

        // Per-step affine maps for t = base..base+KPL-1:
        //   A[j], Bl[j] (lambda), Bs[j]=r[j] (sum)
        float A[KPL], Bl[KPL], Bs[KPL];

        if (full) {
            const float4* r4 = (const float4*)(rrow + base);   // 32B aligned
            const float4* d4 = (const float4*)(drow + base);
            float4 ra = r4[0], rb = r4[1];
            float4 da = d4[0], db = d4[1];
            float r[KPL] = {ra.x, ra.y, ra.z, ra.w, rb.x, rb.y, rb.z, rb.w};
            float d[KPL] = {da.x, da.y, da.z, da.w, db.x, db.y, db.z, db.w};
            float vn[KPL], l[KPL];
            #pragma unroll
            for (int j = 0; j < KPL; j++) vn[j] = __ldg(vrow + base + 1 + j);
            #pragma unroll
            for (int j = 0; j < KPL; j++) l[j] = g_lam_tab[base + j];

            #pragma unroll
            for (int j = 0; j < KPL; j++) {
                float cont = g - g * d[j];               // gamma*(1-done)
                A[j]  = cont * l[j];
                Bl[j] = fmaf(cont - A[j], vn[j], r[j]);  // cont*(1-l)*vn + r
                Bs[j] = r[j];
            }
        } else {
            #pragma unroll
            for (int j = 0; j < KPL; j++) {
                int t = base + j;
                if (t < T) {
                    float r  = rrow[t];
                    float d  = drow[t];
                    float vn = vrow[t + 1];
                    float l  = g_lam_tab[t];
                    float cont = g - g * d;
                    A[j]  = cont * l;
                    Bl[j] = fmaf(cont - A[j], vn, r);
                    Bs[j] = r;
                } else {
                    A[j] = 1.0f; Bl[j] = 0.0f; Bs[j] = 0.0f;  // identity
                }
            }
        }

        // Local composition: S = m_0 ∘ m_1 ∘ ... ∘ m_{KPL-1}
        // (maps x_{base+KPL} -> x_{base})
        float SA = A[KPL - 1], SBl = Bl[KPL - 1], SBs = Bs[KPL - 1];
        #pragma unroll
        for (int j = KPL - 2; j >= 0; --j) {
            SBl = fmaf(A[j], SBl, Bl[j]);
            SBs = fmaf(A[j], SBs, Bs[j]);
            SA  = A[j] * SA;
        }

        // Warp inclusive suffix scan of lane maps.
        #pragma unroll
        for (int len = 1; len < 32; len <<= 1) {
            float Ao  = __shfl_down_sync(FULL_MASK, SA,  len);
            float Blo = __shfl_down_sync(FULL_MASK, SBl, len);
            float Bso = __shfl_down_sync(FULL_MASK, SBs, len);
            if (lane + len < 32) {
                SBl = fmaf(SA, Blo, SBl);
                SBs = fmaf(SA, Bso, SBs);
                SA  = SA * Ao;
            }
        }

        // Incoming state for this lane = S_{lane+1}(carry); lane 31 gets carry.
        float nA  = __shfl_down_sync(FULL_MASK, SA,  1);
        float nBl = __shfl_down_sync(FULL_MASK, SBl, 1);
        float nBs = __shfl_down_sync(FULL_MASK, SBs, 1);
        float xl = (lane == 31) ? c_lam : fmaf(nA, c_lam, nBl);
        float xs = (lane == 31) ? c_sum : fmaf(nA, c_sum, nBs);

        // Local expansion j = KPL-1 .. 0; collect for vectorized stores.
        float outl[KPL], outs[KPL];
        #pragma unroll
        for (int j = KPL - 1; j >= 0; --j) {
            xl = fmaf(A[j], xl, Bl[j]);
            xs = fmaf(A[j], xs, Bs[j]);
            outl[j] = xl;
            outs[j] = xs;
        }

        if (full) {
            // sum rows are 32B-aligned at base -> float4 stores
            float4* s4 = (float4*)(srow + base);
            s4[0] = make_float4(outs[0], outs[1], outs[2], outs[3]);
            s4[1] = make_float4(outs[4], outs[5], outs[6], outs[7]);
            // lam rows (length T+1) are misaligned -> scalar stores
            #pragma unroll
            for (int j = 0; j < KPL; j++) lrow[base + j] = outl[j];
        } else {
            #pragma unroll
            for (int j = 0; j < KPL; j++) {
                if (base + j < T) { lrow[base + j] = outl[j]; srow[base + j] = outs[j]; }
            }
        }

        // New carry = x at t = s*SEG (lane 0's last expanded value).
        c_lam = __shfl_sync(FULL_MASK, xl, 0);
        c_sum = __shfl_sync(FULL_MASK, xs, 0);
    }
}

extern "C" void kernel_launch(void* const* d_in, const int* in_sizes, int n_in,
                              void* d_out, int out_size)
{
    const float* values    = (const float*)d_in[0];
    const float* rewards   = (const float*)d_in[1];
    const float* dones     = (const float*)d_in[2];
    const float* raw_gamma = (const float*)d_in[3];
    const float* raw_lambd = (const float*)d_in[4];
    const int*   p_start   = (n_in > 5) ? (const int*)d_in[5] : nullptr;

    const int T = in_sizes[4];          // raw_lambd has T elements
    const int B = in_sizes[1] / T;      // rewards is B*T

    float* out_lam = (float*)d_out;                       // B*(T+1)
    float* out_sum = (float*)d_out + (size_t)B * (T + 1); // B*T

    prep_kernel<<<(T + 255) / 256, 256>>>(raw_gamma, raw_lambd, p_start, T);

    const int warps_per_block = 4;
    const int threads = warps_per_block * 32;
    const int blocks  = (B + warps_per_block - 1) / warps_per_block;

    td_scan_kernel<<<blocks, threads>>>(
        values, rewards, dones, out_lam, out_sum, B, T);
}

// round 3
// speedup vs baseline: 2.0994x; 1.4211x over previous
#include <cuda_runtime.h>
#include <cstdint>

#define FULL_MASK 0xFFFFFFFFu
#define KPL 8                 // timesteps per lane
#define SEG (32 * KPL)        // 256 timesteps per warp-segment
#define WARPS_PER_BLOCK 4
#define PAD_W 9               // padded words per lane (stride-9: conflict-free)

// Precomputed per-timestep lambda and gamma (written by prep_kernel).
__device__ __align__(16) float g_lam_tab[16384];
__device__ float g_gamma_c;

__global__ void prep_kernel(const float* __restrict__ raw_gamma,
                            const float* __restrict__ raw_lambd,
                            const int*   __restrict__ p_start,
                            int T)
{
    int t = blockIdx.x * blockDim.x + threadIdx.x;
    if (t == 0) {
        g_gamma_c = 0.99f + 0.01f * tanhf(0.5f * raw_gamma[0]);   // 2*sig-1 = tanh(x/2)
    }
    int s0 = p_start ? p_start[0] : 0;
    if (t < T) {
        g_lam_tab[t] = 0.95f + 0.05f * tanhf(0.5f * raw_lambd[s0 + t]);
    }
}

// One warp per batch row. Backward affine scan:
//   x_t = A_t * x_{t+1} + B_t,  A_t = g*(1-d_t)*l_t shared by both recurrences.
__global__ __launch_bounds__(WARPS_PER_BLOCK * 32)
void td_scan_kernel(const float* __restrict__ values,   // [B, T+1]
                    const float* __restrict__ rewards,  // [B, T]
                    const float* __restrict__ dones,    // [B, T]
                    float* __restrict__ out_lam,        // [B, T+1]
                    float* __restrict__ out_sum,        // [B, T]
                    int B, int T)
{
    __shared__ float stage[WARPS_PER_BLOCK][32 * PAD_W];

    const int lane = threadIdx.x & 31;
    const int wid  = threadIdx.x >> 5;
    const int row  = blockIdx.x * WARPS_PER_BLOCK + wid;
    if (row >= B) return;

    float* st = stage[wid];
    const float g = g_gamma_c;

    const float* vrow = values  + (size_t)row * (size_t)(T + 1);
    const float* rrow = rewards + (size_t)row * (size_t)T;
    const float* drow = dones   + (size_t)row * (size_t)T;
    float* lrow = out_lam + (size_t)row * (size_t)(T + 1);
    float* srow = out_sum + (size_t)row * (size_t)T;

    const float vlast = vrow[T];
    if (lane == 0) lrow[T] = vlast;

    float c_lam = vlast;
    float c_sum = 0.0f;

    const int nseg = (T + SEG - 1) / SEG;

    for (int s = nseg - 1; s >= 0; --s) {
        const int segb = s * SEG;
        const int base = segb + lane * KPL;
        const bool full = (segb + SEG <= T);

        float A[KPL], Bl[KPL], Bs[KPL];

        if (full) {
            // rewards/dones rows are 16B-aligned at base -> LDG.128
            const float4* r4 = (const float4*)(rrow + base);
            const float4* d4 = (const float4*)(drow + base);
            float4 ra = r4[0], rb = r4[1];
            float4 da = d4[0], db = d4[1];

            // lambda table is aligned -> LDG.128
            const float4* l4 = (const float4*)(g_lam_tab + base);
            float4 la = l4[0], lb = l4[1];

            // values window [segb+1 .. segb+256]: coalesced scalar loads,
            // transpose through padded smem to per-lane contiguous regs.
            float vt[8];
            const float* vp = vrow + segb + 1;
            #pragma unroll
            for (int k = 0; k < 8; k++) vt[k] = vp[k * 32 + lane];
            #pragma unroll
            for (int k = 0; k < 8; k++) {
                int i = k * 32 + lane;
                st[(i >> 3) * PAD_W + (i & 7)] = vt[k];
            }
            __syncwarp();
            float vn[KPL];
            #pragma unroll
            for (int j = 0; j < KPL; j++) vn[j] = st[lane * PAD_W + j];
            __syncwarp();   // before buffer reuse below

            float r[KPL] = {ra.x, ra.y, ra.z, ra.w, rb.x, rb.y, rb.z, rb.w};
            float d[KPL] = {da.x, da.y, da.z, da.w, db.x, db.y, db.z, db.w};
            float l[KPL] = {la.x, la.y, la.z, la.w, lb.x, lb.y, lb.z, lb.w};

            #pragma unroll
            for (int j = 0; j < KPL; j++) {
                float cont = g - g * d[j];               // gamma*(1-done)
                A[j]  = cont * l[j];
                Bl[j] = fmaf(cont - A[j], vn[j], r[j]);  // cont*(1-l)*vn + r
                Bs[j] = r[j];
            }
        } else {
            #pragma unroll
            for (int j = 0; j < KPL; j++) {
                int t = base + j;
                if (t < T) {
                    float r  = rrow[t];
                    float d  = drow[t];
                    float vn = vrow[t + 1];
                    float l  = g_lam_tab[t];
                    float cont = g - g * d;
                    A[j]  = cont * l;
                    Bl[j] = fmaf(cont - A[j], vn, r);
                    Bs[j] = r;
                } else {
                    A[j] = 1.0f; Bl[j] = 0.0f; Bs[j] = 0.0f;
                }
            }
        }

        // Local composition: S = m_0 ∘ ... ∘ m_{KPL-1}
        float SA = A[KPL - 1], SBl = Bl[KPL - 1], SBs = Bs[KPL - 1];
        #pragma unroll
        for (int j = KPL - 2; j >= 0; --j) {
            SBl = fmaf(A[j], SBl, Bl[j]);
            SBs = fmaf(A[j], SBs, Bs[j]);
            SA  = A[j] * SA;
        }

        // Warp inclusive suffix scan of lane maps.
        #pragma unroll
        for (int len = 1; len < 32; len <<= 1) {
            float Ao  = __shfl_down_sync(FULL_MASK, SA,  len);
            float Blo = __shfl_down_sync(FULL_MASK, SBl, len);
            float Bso = __shfl_down_sync(FULL_MASK, SBs, len);
            if (lane + len < 32) {
                SBl = fmaf(SA, Blo, SBl);
                SBs = fmaf(SA, Bso, SBs);
                SA  = SA * Ao;
            }
        }

        // Incoming state for this lane = composed map of lanes to the right.
        float nA  = __shfl_down_sync(FULL_MASK, SA,  1);
        float nBl = __shfl_down_sync(FULL_MASK, SBl, 1);
        float nBs = __shfl_down_sync(FULL_MASK, SBs, 1);
        float xl = (lane == 31) ? c_lam : fmaf(nA, c_lam, nBl);
        float xs = (lane == 31) ? c_sum : fmaf(nA, c_sum, nBs);

        // Local expansion.
        float outl[KPL], outs[KPL];
        #pragma unroll
        for (int j = KPL - 1; j >= 0; --j) {
            xl = fmaf(A[j], xl, Bl[j]);
            xs = fmaf(A[j], xs, Bs[j]);
            outl[j] = xl;
            outs[j] = xs;
        }

        if (full) {
            // sum rows aligned -> STG.128
            float4* s4 = (float4*)(srow + base);
            s4[0] = make_float4(outs[0], outs[1], outs[2], outs[3]);
            s4[1] = make_float4(outs[4], outs[5], outs[6], outs[7]);

            // lam rows misaligned -> transpose via padded smem, coalesced STG.32
            #pragma unroll
            for (int j = 0; j < KPL; j++) st[lane * PAD_W + j] = outl[j];
            __syncwarp();
            float* lp = lrow + segb;
            #pragma unroll
            for (int k = 0; k < 8; k++) {
                int i = k * 32 + lane;
                lp[i] = st[(i >> 3) * PAD_W + (i & 7)];
            }
            __syncwarp();
        } else {
            #pragma unroll
            for (int j = 0; j < KPL; j++) {
                if (base + j < T) { lrow[base + j] = outl[j]; srow[base + j] = outs[j]; }
            }
        }

        c_lam = __shfl_sync(FULL_MASK, xl, 0);
        c_sum = __shfl_sync(FULL_MASK, xs, 0);
    }
}

extern "C" void kernel_launch(void* const* d_in, const int* in_sizes, int n_in,
                              void* d_out, int out_size)
{
    const float* values    = (const float*)d_in[0];
    const float* rewards   = (const float*)d_in[1];
    const float* dones     = (const float*)d_in[2];
    const float* raw_gamma = (const float*)d_in[3];
    const float* raw_lambd = (const float*)d_in[4];
    const int*   p_start   = (n_in > 5) ? (const int*)d_in[5] : nullptr;

    const int T = in_sizes[4];
    const int B = in_sizes[1] / T;

    float* out_lam = (float*)d_out;                       // B*(T+1)
    float* out_sum = (float*)d_out + (size_t)B * (T + 1); // B*T

    prep_kernel<<<(T + 255) / 256, 256>>>(raw_gamma, raw_lambd, p_start, T);

    const int threads = WARPS_PER_BLOCK * 32;
    const int blocks  = (B + WARPS_PER_BLOCK - 1) / WARPS_PER_BLOCK;

    td_scan_kernel<<<blocks, threads>>>(
        values, rewards, dones, out_lam, out_sum, B, T);
}